// round 6
// baseline (speedup 1.0000x reference)
#include <cuda_runtime.h>
#include <cuda_bf16.h>

#define NB 16        // batches
#define NT 128       // sequential writes
#define NR 2048      // reads
#define ABITS 20
#define VBITS 32
#define RPB 128      // reads per block (== threads)

// Fused build+read kernel.
//  - Each block owns (batch b, read tile). It redundantly rebuilds the
//    associative memory for batch b in shared memory (cheap: 128 entries),
//    then each thread computes one read's softmax-attention output.
//  - Key insight: +/-1 encoded 20-bit addresses => dot == 20 iff identical,
//    and score > 19 in the reference is exactly "address already present".
//    So the sequential scan is a dedupe (first-occurrence slot, last-write
//    value), and read scores are 20 - 2*popc(q ^ key) on packed uint32.
//  - Invalid-entry logits of -1e9 give exp()==0 exactly in fp32, so a
//    softmax over only the valid `count` entries is bit-equivalent.
__global__ __launch_bounds__(RPB) void utvm_kernel(
    const float* __restrict__ waddr,   // [NB, NT, ABITS]
    const float* __restrict__ wval,    // [NB, NT, VBITS]
    const float* __restrict__ raddr,   // [NB, NR, ABITS]
    float* __restrict__ out)           // [NB, NR, VBITS]
{
    const int b   = blockIdx.x;
    const int rb  = blockIdx.y;
    const int tid = threadIdx.x;

    __shared__ unsigned aw[NT];          // packed write addresses
    __shared__ unsigned vw[NT];          // packed write values
    __shared__ int      uniq[NT];
    __shared__ unsigned keys_s[NT];      // packed keys per slot
    __shared__ float    vals_s[NT][VBITS]; // +/-1 expanded values per slot

    // ---- pack this batch's 128 writes (thread t <-> write t) ----
    {
        const float4* ap = reinterpret_cast<const float4*>(
            waddr + ((long)b * NT + tid) * ABITS);      // 80B-aligned
        unsigned a = 0;
        #pragma unroll
        for (int k = 0; k < ABITS / 4; k++) {
            float4 f = ap[k];
            if (f.x > 0.f) a |= 1u << (4 * k + 0);
            if (f.y > 0.f) a |= 1u << (4 * k + 1);
            if (f.z > 0.f) a |= 1u << (4 * k + 2);
            if (f.w > 0.f) a |= 1u << (4 * k + 3);
        }
        aw[tid] = a;

        const float4* vp = reinterpret_cast<const float4*>(
            wval + ((long)b * NT + tid) * VBITS);       // 128B-aligned
        unsigned v = 0;
        #pragma unroll
        for (int k = 0; k < VBITS / 4; k++) {
            float4 f = vp[k];
            if (f.x > 0.f) v |= 1u << (4 * k + 0);
            if (f.y > 0.f) v |= 1u << (4 * k + 1);
            if (f.z > 0.f) v |= 1u << (4 * k + 2);
            if (f.w > 0.f) v |= 1u << (4 * k + 3);
        }
        vw[tid] = v;
    }
    __syncthreads();

    // ---- dedupe: first occurrence wins the slot (argmax tie-break) ----
    {
        unsigned a = aw[tid];
        int first = tid;
        for (int j = 0; j < tid; j++)
            if (aw[j] == a) { first = j; break; }
        uniq[tid] = (first == tid) ? 1 : 0;
    }
    __syncthreads();

    int cnt = 0;
    {
        int slot = 0;
        #pragma unroll 8
        for (int j = 0; j < NT; j++) {
            if (j == tid) slot = cnt;
            cnt += uniq[j];
        }
        if (uniq[tid]) {
            unsigned a = aw[tid];
            unsigned v = vw[tid];                 // last write wins
            for (int j = tid + 1; j < NT; j++)
                if (aw[j] == a) v = vw[j];
            keys_s[slot] = a;
            #pragma unroll
            for (int i = 0; i < VBITS; i++)
                vals_s[slot][i] = ((v >> i) & 1u) ? 1.f : -1.f;
        }
    }
    __syncthreads();

    // ---- read: one thread per read ----
    const int r = rb * RPB + tid;
    unsigned q = 0;
    {
        const float4* rp = reinterpret_cast<const float4*>(
            raddr + ((long)b * NR + r) * ABITS);
        #pragma unroll
        for (int k = 0; k < ABITS / 4; k++) {
            float4 f = rp[k];
            if (f.x > 0.f) q |= 1u << (4 * k + 0);
            if (f.y > 0.f) q |= 1u << (4 * k + 1);
            if (f.z > 0.f) q |= 1u << (4 * k + 2);
            if (f.w > 0.f) q |= 1u << (4 * k + 3);
        }
    }

    // pass 1: min Hamming distance == max score (exact integer max)
    int minpc = 64;
    for (int e = 0; e < cnt; e++) {
        int pc = __popc(q ^ keys_s[e]);
        minpc = min(minpc, pc);
    }

    // pass 2: softmax-weighted combine of +/-1 values
    // logit - maxlogit = TEMP * ((20-2pc) - (20-2minpc)) = 20*(minpc - pc)
    float denom = 0.f;
    float acc[VBITS];
    #pragma unroll
    for (int i = 0; i < VBITS; i++) acc[i] = 0.f;

    for (int e = 0; e < cnt; e++) {
        int pc = __popc(q ^ keys_s[e]);
        float p = __expf(20.0f * (float)(minpc - pc));
        denom += p;
        const float4* vv = reinterpret_cast<const float4*>(vals_s[e]);
        #pragma unroll
        for (int i = 0; i < VBITS / 4; i++) {
            float4 t = vv[i];                     // LDS.128 broadcast
            acc[4 * i + 0] += p * t.x;
            acc[4 * i + 1] += p * t.y;
            acc[4 * i + 2] += p * t.z;
            acc[4 * i + 3] += p * t.w;
        }
    }

    const float inv = 1.0f / denom;
    float4* op = reinterpret_cast<float4*>(out + ((long)b * NR + r) * VBITS);
    #pragma unroll
    for (int i = 0; i < VBITS / 4; i++) {
        float4 t;
        t.x = acc[4 * i + 0] * inv;
        t.y = acc[4 * i + 1] * inv;
        t.z = acc[4 * i + 2] * inv;
        t.w = acc[4 * i + 3] * inv;
        op[i] = t;
    }
}

extern "C" void kernel_launch(void* const* d_in, const int* in_sizes, int n_in,
                              void* d_out, int out_size) {
    // Identify inputs by element count (robust to metadata ordering):
    //   waddr: 16*128*20  = 40960
    //   wval : 16*128*32  = 65536
    //   raddr: 16*2048*20 = 655360
    const float* waddr = nullptr;
    const float* wval  = nullptr;
    const float* raddr = nullptr;
    for (int i = 0; i < n_in; i++) {
        if (in_sizes[i] == NB * NT * ABITS)      waddr = (const float*)d_in[i];
        else if (in_sizes[i] == NB * NT * VBITS) wval  = (const float*)d_in[i];
        else if (in_sizes[i] == NB * NR * ABITS) raddr = (const float*)d_in[i];
    }
    float* out = (float*)d_out;

    dim3 grid(NB, NR / RPB);   // 16 x 16 blocks
    utvm_kernel<<<grid, RPB>>>(waddr, wval, raddr, out);
}

// round 11
// speedup vs baseline: 1.3776x; 1.3776x over previous
#include <cuda_runtime.h>
#include <cuda_bf16.h>

#define NB 16        // batches
#define NT 128       // sequential writes
#define NR 2048      // reads
#define ABITS 20
#define VBITS 32
#define THREADS 512
#define SPLIT 4                  // threads cooperating per read
#define RPB (THREADS / SPLIT)    // 128 reads per block
#define CAP 32                   // per-thread match list (<= ceil(NT/SPLIT))

// Fused build+read kernel, v2.
//  - Softmax with TEMP=10 on integer scores (step 2 in distance) is an argmin
//    to ~2e-9 relative: non-minimal entries weigh exp(-20). So the read is:
//    average of +/-1 values over entries at MIN Hamming distance:
//        out_i = (2*bitcount_i - m) / m          (exact integer arithmetic)
//  - 4 threads per read split the entry scan (stride SPLIT), then combine
//    (minpc, m, SWAR bit counters) with shfl.bfly. Each thread stores its
//    8 output floats (byte-lane of the SWAR counters it owns).
//  - Per entry: LDS.64 (key,val) + XOR + POPC + min tracking; matched values
//    go to a tiny local list, bit-counted afterwards with
//    s[k] += (v>>k) & 0x01010101 (bits k,k+8,k+16,k+24 in byte lanes).
__global__ __launch_bounds__(THREADS) void utvm_kernel(
    const float* __restrict__ waddr,   // [NB, NT, ABITS]
    const float* __restrict__ wval,    // [NB, NT, VBITS]
    const float* __restrict__ raddr,   // [NB, NR, ABITS]
    float* __restrict__ out)           // [NB, NR, VBITS]
{
    const int b   = blockIdx.x;
    const int rb  = blockIdx.y;
    const int tid = threadIdx.x;

    __shared__ unsigned aw[NT];     // packed write addresses
    __shared__ unsigned vw[NT];     // packed write values
    __shared__ int      uniq[NT];
    __shared__ uint2    kv_s[NT];   // (key, last-written value) per slot

    // ---- pack this batch's 128 writes (thread t <-> write t) ----
    if (tid < NT) {
        const float4* ap = reinterpret_cast<const float4*>(
            waddr + ((long)b * NT + tid) * ABITS);
        unsigned a = 0;
        #pragma unroll
        for (int k = 0; k < ABITS / 4; k++) {
            float4 f = ap[k];
            if (f.x > 0.f) a |= 1u << (4 * k + 0);
            if (f.y > 0.f) a |= 1u << (4 * k + 1);
            if (f.z > 0.f) a |= 1u << (4 * k + 2);
            if (f.w > 0.f) a |= 1u << (4 * k + 3);
        }
        aw[tid] = a;

        const float4* vp = reinterpret_cast<const float4*>(
            wval + ((long)b * NT + tid) * VBITS);
        unsigned v = 0;
        #pragma unroll
        for (int k = 0; k < VBITS / 4; k++) {
            float4 f = vp[k];
            if (f.x > 0.f) v |= 1u << (4 * k + 0);
            if (f.y > 0.f) v |= 1u << (4 * k + 1);
            if (f.z > 0.f) v |= 1u << (4 * k + 2);
            if (f.w > 0.f) v |= 1u << (4 * k + 3);
        }
        vw[tid] = v;
    }
    __syncthreads();

    // ---- dedupe: first occurrence wins the slot (argmax tie-break) ----
    if (tid < NT) {
        unsigned a = aw[tid];
        int first = tid;
        for (int j = 0; j < tid; j++)
            if (aw[j] == a) { first = j; break; }
        uniq[tid] = (first == tid) ? 1 : 0;
    }
    __syncthreads();

    int cnt = 0;
    {
        int slot = 0;
        #pragma unroll 8
        for (int j = 0; j < NT; j++) {
            if (j == tid) slot = cnt;
            cnt += uniq[j];
        }
        if (tid < NT && uniq[tid]) {
            unsigned a = aw[tid];
            unsigned v = vw[tid];                 // last write wins
            for (int j = tid + 1; j < NT; j++)
                if (aw[j] == a) v = vw[j];
            kv_s[slot] = make_uint2(a, v);
        }
    }
    __syncthreads();

    // ---- read phase: SPLIT threads per read ----
    const int ridx = tid >> 2;        // read within block
    const int half = tid & (SPLIT - 1);
    const int r    = rb * RPB + ridx;

    unsigned q = 0;
    {
        const float4* rp = reinterpret_cast<const float4*>(
            raddr + ((long)b * NR + r) * ABITS);
        #pragma unroll
        for (int k = 0; k < ABITS / 4; k++) {
            float4 f = rp[k];
            if (f.x > 0.f) q |= 1u << (4 * k + 0);
            if (f.y > 0.f) q |= 1u << (4 * k + 1);
            if (f.z > 0.f) q |= 1u << (4 * k + 2);
            if (f.w > 0.f) q |= 1u << (4 * k + 3);
        }
    }

    // scan my stride-SPLIT share of entries: min distance + matched values
    int minpc = 64;
    int m = 0;
    unsigned vlist[CAP];
    #pragma unroll 4
    for (int e = half; e < cnt; e += SPLIT) {
        uint2 kv = kv_s[e];
        int pc = __popc(q ^ kv.x);
        bool better = pc < minpc;
        if (better) { minpc = pc; m = 0; }
        if (pc == minpc) { vlist[m] = kv.y; m++; }   // m < CAP by construction
    }

    // SWAR bit counts over matched values: s[k] bytes = bits k,k+8,k+16,k+24
    unsigned s[8];
    #pragma unroll
    for (int k = 0; k < 8; k++) s[k] = 0u;
    for (int j = 0; j < m; j++) {
        unsigned v = vlist[j];
        #pragma unroll
        for (int k = 0; k < 8; k++) s[k] += (v >> k) & 0x01010101u;
    }

    // combine across the SPLIT-thread group (lanes 4i..4i+3)
    #pragma unroll
    for (int off = 1; off < SPLIT; off <<= 1) {
        int minpc_o = __shfl_xor_sync(0xFFFFFFFFu, minpc, off);
        int m_o     = __shfl_xor_sync(0xFFFFFFFFu, m, off);
        unsigned so[8];
        #pragma unroll
        for (int k = 0; k < 8; k++)
            so[k] = __shfl_xor_sync(0xFFFFFFFFu, s[k], off);

        bool keep = (minpc <= minpc_o);   // my entries still count
        bool add  = (minpc_o <= minpc);   // their entries count
        int mm = keep ? m : 0;
        if (add) mm += m_o;
        m = mm;
        #pragma unroll
        for (int k = 0; k < 8; k++) {
            unsigned v = keep ? s[k] : 0u;
            if (add) v += so[k];
            s[k] = v;
        }
        minpc = min(minpc, minpc_o);
    }

    // out_i = (2*c_i - m)/m = c_i*(2/m) - 1; thread `half` owns byte lane
    // `half` of every s[k], i.e. output bits [8*half, 8*half+8)
    const float inv2m = 2.0f / (float)m;
    const int sh = half * 8;
    float f[8];
    #pragma unroll
    for (int k = 0; k < 8; k++) {
        int c = (int)((s[k] >> sh) & 0xFFu);
        f[k] = fmaf((float)c, inv2m, -1.0f);
    }

    float4* op = reinterpret_cast<float4*>(
        out + ((long)b * NR + r) * VBITS + half * 8);
    op[0] = make_float4(f[0], f[1], f[2], f[3]);
    op[1] = make_float4(f[4], f[5], f[6], f[7]);
}

extern "C" void kernel_launch(void* const* d_in, const int* in_sizes, int n_in,
                              void* d_out, int out_size) {
    // Identify inputs by element count (robust to metadata ordering):
    //   waddr: 16*128*20  = 40960
    //   wval : 16*128*32  = 65536
    //   raddr: 16*2048*20 = 655360
    const float* waddr = nullptr;
    const float* wval  = nullptr;
    const float* raddr = nullptr;
    for (int i = 0; i < n_in; i++) {
        if (in_sizes[i] == NB * NT * ABITS)      waddr = (const float*)d_in[i];
        else if (in_sizes[i] == NB * NT * VBITS) wval  = (const float*)d_in[i];
        else if (in_sizes[i] == NB * NR * ABITS) raddr = (const float*)d_in[i];
    }
    float* out = (float*)d_out;

    dim3 grid(NB, NR / RPB);   // 16 x 16 blocks, 512 threads each
    utvm_kernel<<<grid, THREADS>>>(waddr, wval, raddr, out);
}